// round 14
// baseline (speedup 1.0000x reference)
#include <cuda_runtime.h>
#include <math.h>
#include <stdint.h>

#define H    1024
#define V    32000
#define B    32
#define T    64
#define G3H  3072
#define NMT  250
#define KSP  4
#define GPITCH 162
#define BPITCH 36
#define OUT_LOGP 65536000LL

// logits tc smem layout (floats)
#define AREG(buf,s,w) ((((buf)*2+(s))*8+(w))*292)
#define BOFF 9344
#define DOFF 11392
#define SMEM_DYN 63488   // (11392 + 4480) * 4 bytes

typedef unsigned long long ull;

__device__ float g_h[2][H * B];
__device__ float g_Cb[KSP][B][2 * G3H];
__device__ float g_hfrag[65536];          // tf32-split h in mma fragment order
__device__ float g_pval[B][NMT];
__device__ int   g_pidx[B][NMT];
__device__ float g_rowmax[B * T];
__device__ int   g_tok[B];

__device__ __forceinline__ ull splat2(float x){ull r;asm("mov.b64 %0, {%1, %1};":"=l"(r):"f"(x));return r;}
__device__ __forceinline__ void fma2(ull&d,ull a,ull b){asm("fma.rn.f32x2 %0, %1, %2, %0;":"+l"(d):"l"(a),"l"(b));}
__device__ __forceinline__ float2 unpk(ull v){float2 f;asm("mov.b64 {%0, %1}, %2;":"=f"(f.x),"=f"(f.y):"l"(v));return f;}
__device__ __forceinline__ int acol(int r){return (r>>3)*10+(r&7);}
__device__ __forceinline__ uint32_t smem_u32(const void*p){uint32_t a;asm("{ .reg .u64 t; cvta.to.shared.u64 t, %1; cvt.u32.u64 %0, t; }":"=r"(a):"l"(p));return a;}
__device__ __forceinline__ uint32_t tf32b(float x){uint32_t u;asm("cvt.rna.tf32.f32 %0, %1;":"=r"(u):"f"(x));return u;}

__global__ void init_k(const float* __restrict__ enc_h){
    int b=blockIdx.x,k=threadIdx.x;
    g_h[0][k*B+b]=enc_h[b*H+k];
    if(b==0&&k<B) g_tok[k]=0;
}

// ============ GRU gates GEMM (unchanged) ============
__global__ void __launch_bounds__(128) gru_gemm(
    const float* __restrict__ Wih,const float* __restrict__ Whh,
    const float* __restrict__ emb,int t)
{
    const int m0=blockIdx.x*128, ks=blockIdx.y;
    const bool ih=(m0<G3H);
    const float* __restrict__ Wm = ih ? (Wih+(size_t)m0*H) : (Whh+(size_t)(m0-G3H)*H);
    const float* __restrict__ hb = g_h[t&1];
    __shared__ float As[32][GPITCH];
    __shared__ float Bs[32][BPITCH];
    __shared__ int srow[B];
    const int tid=threadIdx.x, tm=tid&15, tb=tid>>4, lr=tid>>2, lc=tid&3, bk=tid>>2, bb=(tid&3)*8;

    if(ih){
        if(t>0){
            int b=tid>>2, li=tid&3;
            float v=-INFINITY; int idx=0x7fffffff;
            for(int i=li;i<NMT;i+=4){
                float pv=g_pval[b][i]; int pi=g_pidx[b][i];
                if(pv>v||(pv==v&&pi<idx)){v=pv;idx=pi;}
            }
            #pragma unroll
            for(int off=2;off>0;off>>=1){
                float ov=__shfl_down_sync(0xffffffffu,v,off,4);
                int oi=__shfl_down_sync(0xffffffffu,idx,off,4);
                if(ov>v||(ov==v&&oi<idx)){v=ov;idx=oi;}
            }
            if(li==0){
                srow[b]=idx*H;
                if(blockIdx.x==0&&ks==0) g_rowmax[b*T+(t-1)]=v;
            }
        } else if(tid<B) srow[tid]=0;
        __syncthreads();
    }

    const int kbase=ks*(H/KSP);
    float4 apre[8]; float4 bq0,bq1;
    {
        const int k0=kbase;
        #pragma unroll
        for(int p=0;p<4;p++){
            const float* wr=Wm+(size_t)(p*32+lr)*H+k0;
            apre[p*2+0]=*(const float4*)(wr+4*lc);
            apre[p*2+1]=*(const float4*)(wr+16+4*lc);
        }
        if(ih){
            int kg=k0+bk;
            bq0.x=fmaxf(emb[(size_t)srow[bb+0]+kg],0.f); bq0.y=fmaxf(emb[(size_t)srow[bb+1]+kg],0.f);
            bq0.z=fmaxf(emb[(size_t)srow[bb+2]+kg],0.f); bq0.w=fmaxf(emb[(size_t)srow[bb+3]+kg],0.f);
            bq1.x=fmaxf(emb[(size_t)srow[bb+4]+kg],0.f); bq1.y=fmaxf(emb[(size_t)srow[bb+5]+kg],0.f);
            bq1.z=fmaxf(emb[(size_t)srow[bb+6]+kg],0.f); bq1.w=fmaxf(emb[(size_t)srow[bb+7]+kg],0.f);
        } else {
            bq0=*(const float4*)(hb+(k0+bk)*B+bb);
            bq1=*(const float4*)(hb+(k0+bk)*B+bb+4);
        }
    }

    ull acc[4][4];
    #pragma unroll
    for(int p=0;p<4;p++)
        #pragma unroll
        for(int j=0;j<4;j++) acc[p][j]=0ull;

    for(int kt=0;kt<8;kt++){
        #pragma unroll
        for(int p=0;p<4;p++){
            int col=acol(p*32+lr);
            float4 v0=apre[p*2+0], v1=apre[p*2+1];
            int ka=4*lc, kb2=16+4*lc;
            As[ka+0][col]=v0.x; As[ka+1][col]=v0.y; As[ka+2][col]=v0.z; As[ka+3][col]=v0.w;
            As[kb2+0][col]=v1.x; As[kb2+1][col]=v1.y; As[kb2+2][col]=v1.z; As[kb2+3][col]=v1.w;
        }
        *(float4*)&Bs[bk][bb]=bq0;
        *(float4*)&Bs[bk][bb+4]=bq1;
        __syncthreads();

        if(kt+1<8){
            const int k0=kbase+(kt+1)*32;
            #pragma unroll
            for(int p=0;p<4;p++){
                const float* wr=Wm+(size_t)(p*32+lr)*H+k0;
                apre[p*2+0]=*(const float4*)(wr+4*lc);
                apre[p*2+1]=*(const float4*)(wr+16+4*lc);
            }
            if(ih){
                int kg=k0+bk;
                bq0.x=fmaxf(emb[(size_t)srow[bb+0]+kg],0.f); bq0.y=fmaxf(emb[(size_t)srow[bb+1]+kg],0.f);
                bq0.z=fmaxf(emb[(size_t)srow[bb+2]+kg],0.f); bq0.w=fmaxf(emb[(size_t)srow[bb+3]+kg],0.f);
                bq1.x=fmaxf(emb[(size_t)srow[bb+4]+kg],0.f); bq1.y=fmaxf(emb[(size_t)srow[bb+5]+kg],0.f);
                bq1.z=fmaxf(emb[(size_t)srow[bb+6]+kg],0.f); bq1.w=fmaxf(emb[(size_t)srow[bb+7]+kg],0.f);
            } else {
                bq0=*(const float4*)(hb+(k0+bk)*B+bb);
                bq1=*(const float4*)(hb+(k0+bk)*B+bb+4);
            }
        }

        #pragma unroll 16
        for(int kk=0;kk<32;kk++){
            const float* ab=&As[kk][10*tm];
            ull a0=*(const ull*)(ab+0), a1=*(const ull*)(ab+2), a2=*(const ull*)(ab+4), a3=*(const ull*)(ab+6);
            float4 bv=*(const float4*)&Bs[kk][4*tb];
            ull s;
            s=splat2(bv.x); fma2(acc[0][0],a0,s); fma2(acc[1][0],a1,s); fma2(acc[2][0],a2,s); fma2(acc[3][0],a3,s);
            s=splat2(bv.y); fma2(acc[0][1],a0,s); fma2(acc[1][1],a1,s); fma2(acc[2][1],a2,s); fma2(acc[3][1],a3,s);
            s=splat2(bv.z); fma2(acc[0][2],a0,s); fma2(acc[1][2],a1,s); fma2(acc[2][2],a2,s); fma2(acc[3][2],a3,s);
            s=splat2(bv.w); fma2(acc[0][3],a0,s); fma2(acc[1][3],a1,s); fma2(acc[2][3],a2,s); fma2(acc[3][3],a3,s);
        }
        __syncthreads();
    }

    #pragma unroll
    for(int j=0;j<4;j++){
        int b=4*tb+j;
        float2 p0=unpk(acc[0][j]),p1=unpk(acc[1][j]),p2=unpk(acc[2][j]),p3=unpk(acc[3][j]);
        *(float4*)&g_Cb[ks][b][m0+8*tm]  =make_float4(p0.x,p0.y,p1.x,p1.y);
        *(float4*)&g_Cb[ks][b][m0+8*tm+4]=make_float4(p2.x,p2.y,p3.x,p3.y);
    }
}

// ============ GRU cell + fused tf32-split fragment build of h_new ============
__global__ void __launch_bounds__(256) gru_cell(
    const float* __restrict__ bih,const float* __restrict__ bhh,int t)
{
    int gid=blockIdx.x*256+threadIdx.x;
    int b=gid>>10, j=gid&1023;
    float gir=0.f,giz=0.f,gin=0.f,ghr=0.f,ghz=0.f,ghn=0.f;
    #pragma unroll
    for(int s=0;s<KSP;s++){
        const float* C=g_Cb[s][b];
        gir+=C[j]; giz+=C[H+j]; gin+=C[2*H+j];
        ghr+=C[G3H+j]; ghz+=C[G3H+H+j]; ghn+=C[G3H+2*H+j];
    }
    float r=1.f/(1.f+expf(-(gir+bih[j]+ghr+bhh[j])));
    float z=1.f/(1.f+expf(-(giz+bih[H+j]+ghz+bhh[H+j])));
    float n=tanhf(gin+bih[2*H+j]+r*(ghn+bhh[2*H+j]));
    float hold=g_h[t&1][j*B+b];
    float hnew=(1.f-z)*n+z*hold;
    g_h[(t+1)&1][j*B+b]=hnew;

    // fragment-ordered tf32 split: m16n8k8 B operand (k x n col-frag)
    // k=j, n=b: s=k>>3, jn=b>>3, lane=(b&7)*4+(k&3), slot=(k&4)?2:0
    uint32_t hi=tf32b(hnew);
    float lov=hnew-__uint_as_float(hi);
    uint32_t lo=tf32b(lov);
    int base=((((j>>3)*4+(b>>3))*32 + ((b&7)*4+(j&3)))<<2) + ((j&4)?2:0);
    g_hfrag[base]=__uint_as_float(hi);
    g_hfrag[base+1]=__uint_as_float(lo);
}

// ============ Logits via mma.sync tf32 3-split ============
// M=128 (grid 250), N=32, K=1024 in 64 chunks of 16, double-buffered.
__global__ void __launch_bounds__(256) logits_tc(
    const float* __restrict__ Wout,const float* __restrict__ bout,
    float* __restrict__ out,int t)
{
    extern __shared__ float sm[];
    const uint32_t sb=smem_u32(sm);
    const int tid=threadIdx.x, w=tid>>5, lane=tid&31;
    const int mt=blockIdx.x, m0=mt*128;
    const float* __restrict__ Wm=Wout+(size_t)m0*H;
    const int lr=tid>>2, lc=tid&3;

    float4 ap0,ap1,bf;
    ap0=*(const float4*)(Wm+(size_t)lr*H+lc*4);
    ap1=*(const float4*)(Wm+(size_t)(64+lr)*H+lc*4);
    bf=*(const float4*)(g_hfrag+tid*4);

    float acc[4][4];
    #pragma unroll
    for(int j=0;j<4;j++)
        #pragma unroll
        for(int e=0;e<4;e++) acc[j][e]=0.f;

    for(int c=0;c<64;c++){
        const int buf=c&1;
        // stage A hi/lo (interleaved) into fragment tiles
        #pragma unroll
        for(int p=0;p<2;p++){
            int m=p*64+lr;
            const float* v4 = p ? (const float*)&ap1 : (const float*)&ap0;
            uint32_t base=sb+((AREG(buf,(lc>>1),(m>>4)) + (m&15)*18 + (lc&1)*8)<<2);
            #pragma unroll
            for(int i=0;i<4;i++){
                float v=v4[i];
                uint32_t hb_=tf32b(v);
                float lov=v-__uint_as_float(hb_);
                uint32_t lb_=tf32b(lov);
                asm volatile("st.shared.v2.b32 [%0], {%1, %2};"::"r"(base+i*8),"r"(hb_),"r"(lb_):"memory");
            }
        }
        // stage B fragments
        *(float4*)&sm[BOFF + buf*1024 + tid*4] = bf;
        // prefetch next chunk
        if(c+1<64){
            const int k0=(c+1)*16;
            ap0=*(const float4*)(Wm+(size_t)lr*H+k0+lc*4);
            ap1=*(const float4*)(Wm+(size_t)(64+lr)*H+k0+lc*4);
            bf=*(const float4*)(g_hfrag+(c+1)*1024+tid*4);
        }
        __syncthreads();

        #pragma unroll
        for(int s=0;s<2;s++){
            uint32_t ab=sb+((AREG(buf,s,w) + (lane>>2)*18 + (lane&3)*2)<<2);
            uint32_t ah0,al0,ah1,al1,ah2,al2,ah3,al3;
            asm volatile("ld.shared.v2.b32 {%0, %1}, [%2];":"=r"(ah0),"=r"(al0):"r"(ab));
            asm volatile("ld.shared.v2.b32 {%0, %1}, [%2];":"=r"(ah1),"=r"(al1):"r"(ab+576));
            asm volatile("ld.shared.v2.b32 {%0, %1}, [%2];":"=r"(ah2),"=r"(al2):"r"(ab+32));
            asm volatile("ld.shared.v2.b32 {%0, %1}, [%2];":"=r"(ah3),"=r"(al3):"r"(ab+608));
            #pragma unroll
            for(int j=0;j<4;j++){
                uint32_t b0h,b0l,b1h,b1l;
                uint32_t bb2=sb+((BOFF + buf*1024 + ((s*4+j)*32+lane)*4)<<2);
                asm volatile("ld.shared.v4.b32 {%0, %1, %2, %3}, [%4];"
                    :"=r"(b0h),"=r"(b0l),"=r"(b1h),"=r"(b1l):"r"(bb2));
                asm volatile("mma.sync.aligned.m16n8k8.row.col.f32.tf32.tf32.f32 "
                    "{%0,%1,%2,%3},{%4,%5,%6,%7},{%8,%9},{%0,%1,%2,%3};"
                    :"+f"(acc[j][0]),"+f"(acc[j][1]),"+f"(acc[j][2]),"+f"(acc[j][3])
                    :"r"(ah0),"r"(ah1),"r"(ah2),"r"(ah3),"r"(b0h),"r"(b1h));
                asm volatile("mma.sync.aligned.m16n8k8.row.col.f32.tf32.tf32.f32 "
                    "{%0,%1,%2,%3},{%4,%5,%6,%7},{%8,%9},{%0,%1,%2,%3};"
                    :"+f"(acc[j][0]),"+f"(acc[j][1]),"+f"(acc[j][2]),"+f"(acc[j][3])
                    :"r"(ah0),"r"(ah1),"r"(ah2),"r"(ah3),"r"(b0l),"r"(b1l));
                asm volatile("mma.sync.aligned.m16n8k8.row.col.f32.tf32.tf32.f32 "
                    "{%0,%1,%2,%3},{%4,%5,%6,%7},{%8,%9},{%0,%1,%2,%3};"
                    :"+f"(acc[j][0]),"+f"(acc[j][1]),"+f"(acc[j][2]),"+f"(acc[j][3])
                    :"r"(al0),"r"(al1),"r"(al2),"r"(al3),"r"(b0h),"r"(b1h));
            }
        }
    }

    // transpose via smem D[32 b][stride 140]
    {
        int row=lane>>2, colb=(lane&3)*2;
        #pragma unroll
        for(int j=0;j<4;j++){
            int b=j*8+colb;
            sm[DOFF + b*140     + w*16 + row    ]=acc[j][0];
            sm[DOFF + (b+1)*140 + w*16 + row    ]=acc[j][1];
            sm[DOFF + b*140     + w*16 + row + 8]=acc[j][2];
            sm[DOFF + (b+1)*140 + w*16 + row + 8]=acc[j][3];
        }
    }
    __syncthreads();
    // bias + store + argmax partials
    {
        int rb=tid>>3, cc=(tid&7)*16;
        float* orow=out+((size_t)rb*T+t)*V+m0+cc;
        float bv=-INFINITY; int bi=0;
        #pragma unroll
        for(int q=0;q<4;q++){
            float4 v=*(float4*)&sm[DOFF + rb*140 + cc + q*4];
            float4 bs=*(const float4*)&bout[m0+cc+q*4];
            v.x+=bs.x; v.y+=bs.y; v.z+=bs.z; v.w+=bs.w;
            *(float4*)(orow+q*4)=v;
            if(v.x>bv){bv=v.x;bi=q*4+0;}
            if(v.y>bv){bv=v.y;bi=q*4+1;}
            if(v.z>bv){bv=v.z;bi=q*4+2;}
            if(v.w>bv){bv=v.w;bi=q*4+3;}
        }
        int gidx=m0+cc+bi;
        #pragma unroll
        for(int off=4;off>0;off>>=1){
            float ov=__shfl_down_sync(0xffffffffu,bv,off,8);
            int oi=__shfl_down_sync(0xffffffffu,gidx,off,8);
            if(ov>bv||(ov==bv&&oi<gidx)){bv=ov;gidx=oi;}
        }
        if((tid&7)==0){ g_pval[rb][mt]=bv; g_pidx[rb][mt]=gidx; }
    }
}

__global__ void __launch_bounds__(1024) argmax_last(int t)
{
    int b=threadIdx.x>>5, lane=threadIdx.x&31;
    float v=-INFINITY; int idx=0x7fffffff;
    for(int i=lane;i<NMT;i+=32){
        float pv=g_pval[b][i]; int pi=g_pidx[b][i];
        if(pv>v||(pv==v&&pi<idx)){v=pv;idx=pi;}
    }
    #pragma unroll
    for(int off=16;off>0;off>>=1){
        float ov=__shfl_down_sync(0xffffffffu,v,off);
        int oi=__shfl_down_sync(0xffffffffu,idx,off);
        if(ov>v||(ov==v&&oi<idx)){v=ov;idx=oi;}
    }
    if(lane==0){ g_tok[b]=idx; g_rowmax[b*T+t]=v; }
}

__global__ void __launch_bounds__(256) lsm_k(float* __restrict__ out)
{
    __shared__ float red[256];
    int r=blockIdx.x;
    float4* row4=(float4*)(out+(size_t)r*V);
    float mx=g_rowmax[r];
    float s=0.f;
    for(int i=threadIdx.x;i<V/4;i+=256){
        float4 v=row4[i];
        s+=expf(v.x-mx)+expf(v.y-mx)+expf(v.z-mx)+expf(v.w-mx);
    }
    red[threadIdx.x]=s;
    __syncthreads();
    for(int off=128;off>0;off>>=1){
        if(threadIdx.x<off) red[threadIdx.x]+=red[threadIdx.x+off];
        __syncthreads();
    }
    float c=mx+logf(red[0]);
    for(int i=threadIdx.x;i<V/4;i+=256){
        float4 v=row4[i];
        v.x-=c; v.y-=c; v.z-=c; v.w-=c;
        row4[i]=v;
    }
}

__global__ void copy_h(float* __restrict__ dst)
{
    int b=blockIdx.x, k=threadIdx.x;
    dst[b*H+k]=g_h[0][k*B+b];
}

extern "C" void kernel_launch(void* const* d_in,const int* in_sizes,int n_in,
                              void* d_out,int out_size)
{
    const float* enc_h=(const float*)d_in[1];
    const float* emb  =(const float*)d_in[2];
    const float* Wih  =(const float*)d_in[3];
    const float* Whh  =(const float*)d_in[4];
    const float* bih  =(const float*)d_in[5];
    const float* bhh  =(const float*)d_in[6];
    const float* Wout =(const float*)d_in[7];
    const float* bout =(const float*)d_in[8];
    float* out=(float*)d_out;

    cudaFuncSetAttribute(logits_tc,cudaFuncAttributeMaxDynamicSharedMemorySize,SMEM_DYN);

    init_k<<<B,H>>>(enc_h);
    for(int t=0;t<T;t++){
        gru_gemm<<<dim3(48,KSP),128>>>(Wih,Whh,emb,t);
        gru_cell<<<128,256>>>(bih,bhh,t);
        logits_tc<<<NMT,256,SMEM_DYN>>>(Wout,bout,out,t);
    }
    argmax_last<<<1,1024>>>(T-1);
    lsm_k<<<B*T,256>>>(out);
    if((long long)out_size>=OUT_LOGP+(long long)B*H)
        copy_h<<<B,H>>>(out+OUT_LOGP);
}

// round 15
// speedup vs baseline: 1.5402x; 1.5402x over previous
#include <cuda_runtime.h>
#include <math.h>
#include <stdint.h>

#define H    1024
#define V    32000
#define B    32
#define T    64
#define G3H  3072
#define NMT  250
#define KSP  4
#define GPITCH 162
#define BPITCH 36
#define OUT_LOGP 65536000LL

// logits tc smem layout (floats)
#define AREG(buf,s,w) ((((buf)*2+(s))*8+(w))*292)
#define BOFF 9344
#define DOFF 11392
#define SMEM_DYN 63488   // (11392 + 4480) * 4 bytes

typedef unsigned long long ull;

__device__ float g_h[2][H * B];
__device__ float g_Cb[KSP][B][2 * G3H];
__device__ float g_hfrag[65536];          // tf32-split h in mma fragment order
__device__ float g_pval[B][NMT];
__device__ int   g_pidx[B][NMT];
__device__ float g_rowmax[B * T];
__device__ int   g_tok[B];

__device__ __forceinline__ ull splat2(float x){ull r;asm("mov.b64 %0, {%1, %1};":"=l"(r):"f"(x));return r;}
__device__ __forceinline__ void fma2(ull&d,ull a,ull b){asm("fma.rn.f32x2 %0, %1, %2, %0;":"+l"(d):"l"(a),"l"(b));}
__device__ __forceinline__ float2 unpk(ull v){float2 f;asm("mov.b64 {%0, %1}, %2;":"=f"(f.x),"=f"(f.y):"l"(v));return f;}
__device__ __forceinline__ int acol(int r){return (r>>3)*10+(r&7);}
__device__ __forceinline__ uint32_t smem_u32(const void*p){uint32_t a;asm("{ .reg .u64 t; cvta.to.shared.u64 t, %1; cvt.u32.u64 %0, t; }":"=r"(a):"l"(p));return a;}
__device__ __forceinline__ uint32_t tf32b(float x){uint32_t u;asm("cvt.rna.tf32.f32 %0, %1;":"=r"(u):"f"(x));return u;}

__global__ void init_k(const float* __restrict__ enc_h){
    int b=blockIdx.x,k=threadIdx.x;
    g_h[0][k*B+b]=enc_h[b*H+k];
    if(b==0&&k<B) g_tok[k]=0;
}

// ============ GRU gates GEMM (unchanged) ============
__global__ void __launch_bounds__(128) gru_gemm(
    const float* __restrict__ Wih,const float* __restrict__ Whh,
    const float* __restrict__ emb,int t)
{
    const int m0=blockIdx.x*128, ks=blockIdx.y;
    const bool ih=(m0<G3H);
    const float* __restrict__ Wm = ih ? (Wih+(size_t)m0*H) : (Whh+(size_t)(m0-G3H)*H);
    const float* __restrict__ hb = g_h[t&1];
    __shared__ float As[32][GPITCH];
    __shared__ float Bs[32][BPITCH];
    __shared__ int srow[B];
    const int tid=threadIdx.x, tm=tid&15, tb=tid>>4, lr=tid>>2, lc=tid&3, bk=tid>>2, bb=(tid&3)*8;

    if(ih){
        if(t>0){
            int b=tid>>2, li=tid&3;
            float v=-INFINITY; int idx=0x7fffffff;
            for(int i=li;i<NMT;i+=4){
                float pv=g_pval[b][i]; int pi=g_pidx[b][i];
                if(pv>v||(pv==v&&pi<idx)){v=pv;idx=pi;}
            }
            #pragma unroll
            for(int off=2;off>0;off>>=1){
                float ov=__shfl_down_sync(0xffffffffu,v,off,4);
                int oi=__shfl_down_sync(0xffffffffu,idx,off,4);
                if(ov>v||(ov==v&&oi<idx)){v=ov;idx=oi;}
            }
            if(li==0){
                srow[b]=idx*H;
                if(blockIdx.x==0&&ks==0) g_rowmax[b*T+(t-1)]=v;
            }
        } else if(tid<B) srow[tid]=0;
        __syncthreads();
    }

    const int kbase=ks*(H/KSP);
    float4 apre[8]; float4 bq0,bq1;
    {
        const int k0=kbase;
        #pragma unroll
        for(int p=0;p<4;p++){
            const float* wr=Wm+(size_t)(p*32+lr)*H+k0;
            apre[p*2+0]=*(const float4*)(wr+4*lc);
            apre[p*2+1]=*(const float4*)(wr+16+4*lc);
        }
        if(ih){
            int kg=k0+bk;
            bq0.x=fmaxf(emb[(size_t)srow[bb+0]+kg],0.f); bq0.y=fmaxf(emb[(size_t)srow[bb+1]+kg],0.f);
            bq0.z=fmaxf(emb[(size_t)srow[bb+2]+kg],0.f); bq0.w=fmaxf(emb[(size_t)srow[bb+3]+kg],0.f);
            bq1.x=fmaxf(emb[(size_t)srow[bb+4]+kg],0.f); bq1.y=fmaxf(emb[(size_t)srow[bb+5]+kg],0.f);
            bq1.z=fmaxf(emb[(size_t)srow[bb+6]+kg],0.f); bq1.w=fmaxf(emb[(size_t)srow[bb+7]+kg],0.f);
        } else {
            bq0=*(const float4*)(hb+(k0+bk)*B+bb);
            bq1=*(const float4*)(hb+(k0+bk)*B+bb+4);
        }
    }

    ull acc[4][4];
    #pragma unroll
    for(int p=0;p<4;p++)
        #pragma unroll
        for(int j=0;j<4;j++) acc[p][j]=0ull;

    for(int kt=0;kt<8;kt++){
        #pragma unroll
        for(int p=0;p<4;p++){
            int col=acol(p*32+lr);
            float4 v0=apre[p*2+0], v1=apre[p*2+1];
            int ka=4*lc, kb2=16+4*lc;
            As[ka+0][col]=v0.x; As[ka+1][col]=v0.y; As[ka+2][col]=v0.z; As[ka+3][col]=v0.w;
            As[kb2+0][col]=v1.x; As[kb2+1][col]=v1.y; As[kb2+2][col]=v1.z; As[kb2+3][col]=v1.w;
        }
        *(float4*)&Bs[bk][bb]=bq0;
        *(float4*)&Bs[bk][bb+4]=bq1;
        __syncthreads();

        if(kt+1<8){
            const int k0=kbase+(kt+1)*32;
            #pragma unroll
            for(int p=0;p<4;p++){
                const float* wr=Wm+(size_t)(p*32+lr)*H+k0;
                apre[p*2+0]=*(const float4*)(wr+4*lc);
                apre[p*2+1]=*(const float4*)(wr+16+4*lc);
            }
            if(ih){
                int kg=k0+bk;
                bq0.x=fmaxf(emb[(size_t)srow[bb+0]+kg],0.f); bq0.y=fmaxf(emb[(size_t)srow[bb+1]+kg],0.f);
                bq0.z=fmaxf(emb[(size_t)srow[bb+2]+kg],0.f); bq0.w=fmaxf(emb[(size_t)srow[bb+3]+kg],0.f);
                bq1.x=fmaxf(emb[(size_t)srow[bb+4]+kg],0.f); bq1.y=fmaxf(emb[(size_t)srow[bb+5]+kg],0.f);
                bq1.z=fmaxf(emb[(size_t)srow[bb+6]+kg],0.f); bq1.w=fmaxf(emb[(size_t)srow[bb+7]+kg],0.f);
            } else {
                bq0=*(const float4*)(hb+(k0+bk)*B+bb);
                bq1=*(const float4*)(hb+(k0+bk)*B+bb+4);
            }
        }

        #pragma unroll 16
        for(int kk=0;kk<32;kk++){
            const float* ab=&As[kk][10*tm];
            ull a0=*(const ull*)(ab+0), a1=*(const ull*)(ab+2), a2=*(const ull*)(ab+4), a3=*(const ull*)(ab+6);
            float4 bv=*(const float4*)&Bs[kk][4*tb];
            ull s;
            s=splat2(bv.x); fma2(acc[0][0],a0,s); fma2(acc[1][0],a1,s); fma2(acc[2][0],a2,s); fma2(acc[3][0],a3,s);
            s=splat2(bv.y); fma2(acc[0][1],a0,s); fma2(acc[1][1],a1,s); fma2(acc[2][1],a2,s); fma2(acc[3][1],a3,s);
            s=splat2(bv.z); fma2(acc[0][2],a0,s); fma2(acc[1][2],a1,s); fma2(acc[2][2],a2,s); fma2(acc[3][2],a3,s);
            s=splat2(bv.w); fma2(acc[0][3],a0,s); fma2(acc[1][3],a1,s); fma2(acc[2][3],a2,s); fma2(acc[3][3],a3,s);
        }
        __syncthreads();
    }

    #pragma unroll
    for(int j=0;j<4;j++){
        int b=4*tb+j;
        float2 p0=unpk(acc[0][j]),p1=unpk(acc[1][j]),p2=unpk(acc[2][j]),p3=unpk(acc[3][j]);
        *(float4*)&g_Cb[ks][b][m0+8*tm]  =make_float4(p0.x,p0.y,p1.x,p1.y);
        *(float4*)&g_Cb[ks][b][m0+8*tm+4]=make_float4(p2.x,p2.y,p3.x,p3.y);
    }
}

// ============ GRU cell + fused tf32-split fragment build of h_new ============
__global__ void __launch_bounds__(256) gru_cell(
    const float* __restrict__ bih,const float* __restrict__ bhh,int t)
{
    int gid=blockIdx.x*256+threadIdx.x;
    int b=gid>>10, j=gid&1023;
    float gir=0.f,giz=0.f,gin=0.f,ghr=0.f,ghz=0.f,ghn=0.f;
    #pragma unroll
    for(int s=0;s<KSP;s++){
        const float* C=g_Cb[s][b];
        gir+=C[j]; giz+=C[H+j]; gin+=C[2*H+j];
        ghr+=C[G3H+j]; ghz+=C[G3H+H+j]; ghn+=C[G3H+2*H+j];
    }
    float r=1.f/(1.f+expf(-(gir+bih[j]+ghr+bhh[j])));
    float z=1.f/(1.f+expf(-(giz+bih[H+j]+ghz+bhh[H+j])));
    float n=tanhf(gin+bih[2*H+j]+r*(ghn+bhh[2*H+j]));
    float hold=g_h[t&1][j*B+b];
    float hnew=(1.f-z)*n+z*hold;
    g_h[(t+1)&1][j*B+b]=hnew;

    // fragment-ordered tf32 split: m16n8k8 B operand (k x n col-frag)
    // k=j, n=b: s=k>>3, jn=b>>3, lane=(b&7)*4+(k&3), slot=(k&4)?2:0
    uint32_t hi=tf32b(hnew);
    float lov=hnew-__uint_as_float(hi);
    uint32_t lo=tf32b(lov);
    int base=((((j>>3)*4+(b>>3))*32 + ((b&7)*4+(j&3)))<<2) + ((j&4)?2:0);
    g_hfrag[base]=__uint_as_float(hi);
    g_hfrag[base+1]=__uint_as_float(lo);
}

// ============ Logits via mma.sync tf32 3-split ============
// M=128 (grid 250), N=32, K=1024 in 64 chunks of 16, double-buffered.
__global__ void __launch_bounds__(256) logits_tc(
    const float* __restrict__ Wout,const float* __restrict__ bout,
    float* __restrict__ out,int t)
{
    extern __shared__ float sm[];
    const uint32_t sb=smem_u32(sm);
    const int tid=threadIdx.x, w=tid>>5, lane=tid&31;
    const int mt=blockIdx.x, m0=mt*128;
    const float* __restrict__ Wm=Wout+(size_t)m0*H;
    const int lr=tid>>2, lc=tid&3;

    float4 ap0,ap1,bf;
    ap0=*(const float4*)(Wm+(size_t)lr*H+lc*4);
    ap1=*(const float4*)(Wm+(size_t)(64+lr)*H+lc*4);
    bf=*(const float4*)(g_hfrag+tid*4);

    float acc[4][4];
    #pragma unroll
    for(int j=0;j<4;j++)
        #pragma unroll
        for(int e=0;e<4;e++) acc[j][e]=0.f;

    for(int c=0;c<64;c++){
        const int buf=c&1;
        // stage A hi/lo (interleaved) into fragment tiles
        #pragma unroll
        for(int p=0;p<2;p++){
            int m=p*64+lr;
            const float* v4 = p ? (const float*)&ap1 : (const float*)&ap0;
            uint32_t base=sb+((AREG(buf,(lc>>1),(m>>4)) + (m&15)*18 + (lc&1)*8)<<2);
            #pragma unroll
            for(int i=0;i<4;i++){
                float v=v4[i];
                uint32_t hb_=tf32b(v);
                float lov=v-__uint_as_float(hb_);
                uint32_t lb_=tf32b(lov);
                asm volatile("st.shared.v2.b32 [%0], {%1, %2};"::"r"(base+i*8),"r"(hb_),"r"(lb_):"memory");
            }
        }
        // stage B fragments
        *(float4*)&sm[BOFF + buf*1024 + tid*4] = bf;
        // prefetch next chunk
        if(c+1<64){
            const int k0=(c+1)*16;
            ap0=*(const float4*)(Wm+(size_t)lr*H+k0+lc*4);
            ap1=*(const float4*)(Wm+(size_t)(64+lr)*H+k0+lc*4);
            bf=*(const float4*)(g_hfrag+(c+1)*1024+tid*4);
        }
        __syncthreads();

        #pragma unroll
        for(int s=0;s<2;s++){
            uint32_t ab=sb+((AREG(buf,s,w) + (lane>>2)*18 + (lane&3)*2)<<2);
            uint32_t ah0,al0,ah1,al1,ah2,al2,ah3,al3;
            asm volatile("ld.shared.v2.b32 {%0, %1}, [%2];":"=r"(ah0),"=r"(al0):"r"(ab));
            asm volatile("ld.shared.v2.b32 {%0, %1}, [%2];":"=r"(ah1),"=r"(al1):"r"(ab+576));
            asm volatile("ld.shared.v2.b32 {%0, %1}, [%2];":"=r"(ah2),"=r"(al2):"r"(ab+32));
            asm volatile("ld.shared.v2.b32 {%0, %1}, [%2];":"=r"(ah3),"=r"(al3):"r"(ab+608));
            #pragma unroll
            for(int j=0;j<4;j++){
                uint32_t b0h,b0l,b1h,b1l;
                uint32_t bb2=sb+((BOFF + buf*1024 + ((s*4+j)*32+lane)*4)<<2);
                asm volatile("ld.shared.v4.b32 {%0, %1, %2, %3}, [%4];"
                    :"=r"(b0h),"=r"(b0l),"=r"(b1h),"=r"(b1l):"r"(bb2));
                asm volatile("mma.sync.aligned.m16n8k8.row.col.f32.tf32.tf32.f32 "
                    "{%0,%1,%2,%3},{%4,%5,%6,%7},{%8,%9},{%0,%1,%2,%3};"
                    :"+f"(acc[j][0]),"+f"(acc[j][1]),"+f"(acc[j][2]),"+f"(acc[j][3])
                    :"r"(ah0),"r"(ah1),"r"(ah2),"r"(ah3),"r"(b0h),"r"(b1h));
                asm volatile("mma.sync.aligned.m16n8k8.row.col.f32.tf32.tf32.f32 "
                    "{%0,%1,%2,%3},{%4,%5,%6,%7},{%8,%9},{%0,%1,%2,%3};"
                    :"+f"(acc[j][0]),"+f"(acc[j][1]),"+f"(acc[j][2]),"+f"(acc[j][3])
                    :"r"(ah0),"r"(ah1),"r"(ah2),"r"(ah3),"r"(b0l),"r"(b1l));
                asm volatile("mma.sync.aligned.m16n8k8.row.col.f32.tf32.tf32.f32 "
                    "{%0,%1,%2,%3},{%4,%5,%6,%7},{%8,%9},{%0,%1,%2,%3};"
                    :"+f"(acc[j][0]),"+f"(acc[j][1]),"+f"(acc[j][2]),"+f"(acc[j][3])
                    :"r"(al0),"r"(al1),"r"(al2),"r"(al3),"r"(b0h),"r"(b1h));
            }
        }
    }

    // transpose via smem D[32 b][stride 140]
    {
        int row=lane>>2, colb=(lane&3)*2;
        #pragma unroll
        for(int j=0;j<4;j++){
            int b=j*8+colb;
            sm[DOFF + b*140     + w*16 + row    ]=acc[j][0];
            sm[DOFF + (b+1)*140 + w*16 + row    ]=acc[j][1];
            sm[DOFF + b*140     + w*16 + row + 8]=acc[j][2];
            sm[DOFF + (b+1)*140 + w*16 + row + 8]=acc[j][3];
        }
    }
    __syncthreads();
    // bias + store + argmax partials
    {
        int rb=tid>>3, cc=(tid&7)*16;
        float* orow=out+((size_t)rb*T+t)*V+m0+cc;
        float bv=-INFINITY; int bi=0;
        #pragma unroll
        for(int q=0;q<4;q++){
            float4 v=*(float4*)&sm[DOFF + rb*140 + cc + q*4];
            float4 bs=*(const float4*)&bout[m0+cc+q*4];
            v.x+=bs.x; v.y+=bs.y; v.z+=bs.z; v.w+=bs.w;
            *(float4*)(orow+q*4)=v;
            if(v.x>bv){bv=v.x;bi=q*4+0;}
            if(v.y>bv){bv=v.y;bi=q*4+1;}
            if(v.z>bv){bv=v.z;bi=q*4+2;}
            if(v.w>bv){bv=v.w;bi=q*4+3;}
        }
        int gidx=m0+cc+bi;
        #pragma unroll
        for(int off=4;off>0;off>>=1){
            float ov=__shfl_down_sync(0xffffffffu,bv,off,8);
            int oi=__shfl_down_sync(0xffffffffu,gidx,off,8);
            if(ov>bv||(ov==bv&&oi<gidx)){bv=ov;gidx=oi;}
        }
        if((tid&7)==0){ g_pval[rb][mt]=bv; g_pidx[rb][mt]=gidx; }
    }
}

__global__ void __launch_bounds__(1024) argmax_last(int t)
{
    int b=threadIdx.x>>5, lane=threadIdx.x&31;
    float v=-INFINITY; int idx=0x7fffffff;
    for(int i=lane;i<NMT;i+=32){
        float pv=g_pval[b][i]; int pi=g_pidx[b][i];
        if(pv>v||(pv==v&&pi<idx)){v=pv;idx=pi;}
    }
    #pragma unroll
    for(int off=16;off>0;off>>=1){
        float ov=__shfl_down_sync(0xffffffffu,v,off);
        int oi=__shfl_down_sync(0xffffffffu,idx,off);
        if(ov>v||(ov==v&&oi<idx)){v=ov;idx=oi;}
    }
    if(lane==0){ g_tok[b]=idx; g_rowmax[b*T+t]=v; }
}

__global__ void __launch_bounds__(256) lsm_k(float* __restrict__ out)
{
    __shared__ float red[256];
    int r=blockIdx.x;
    float4* row4=(float4*)(out+(size_t)r*V);
    float mx=g_rowmax[r];
    float s=0.f;
    for(int i=threadIdx.x;i<V/4;i+=256){
        float4 v=row4[i];
        s+=expf(v.x-mx)+expf(v.y-mx)+expf(v.z-mx)+expf(v.w-mx);
    }
    red[threadIdx.x]=s;
    __syncthreads();
    for(int off=128;off>0;off>>=1){
        if(threadIdx.x<off) red[threadIdx.x]+=red[threadIdx.x+off];
        __syncthreads();
    }
    float c=mx+logf(red[0]);
    for(int i=threadIdx.x;i<V/4;i+=256){
        float4 v=row4[i];
        v.x-=c; v.y-=c; v.z-=c; v.w-=c;
        row4[i]=v;
    }
}

__global__ void copy_h(float* __restrict__ dst)
{
    int b=blockIdx.x, k=threadIdx.x;
    dst[b*H+k]=g_h[0][k*B+b];
}

extern "C" void kernel_launch(void* const* d_in,const int* in_sizes,int n_in,
                              void* d_out,int out_size)
{
    const float* enc_h=(const float*)d_in[1];
    const float* emb  =(const float*)d_in[2];
    const float* Wih  =(const float*)d_in[3];
    const float* Whh  =(const float*)d_in[4];
    const float* bih  =(const float*)d_in[5];
    const float* bhh  =(const float*)d_in[6];
    const float* Wout =(const float*)d_in[7];
    const float* bout =(const float*)d_in[8];
    float* out=(float*)d_out;

    cudaFuncSetAttribute(logits_tc,cudaFuncAttributeMaxDynamicSharedMemorySize,SMEM_DYN);

    init_k<<<B,H>>>(enc_h);
    for(int t=0;t<T;t++){
        gru_gemm<<<dim3(48,KSP),128>>>(Wih,Whh,emb,t);
        gru_cell<<<128,256>>>(bih,bhh,t);
        logits_tc<<<NMT,256,SMEM_DYN>>>(Wout,bout,out,t);
    }
    argmax_last<<<1,1024>>>(T-1);
    lsm_k<<<B*T,256>>>(out);
    if((long long)out_size>=OUT_LOGP+(long long)B*H)
        copy_h<<<B,H>>>(out+OUT_LOGP);
}